// round 16
// baseline (speedup 1.0000x reference)
#include <cuda_runtime.h>
#include <math.h>
#include <stdint.h>

#define N_NODES 160000
#define N_EDGES 640000
#define N_GRAPHS 8000
#define NPG 20
#define F0 74
#define H 63
#define MAXD 10
#define PH 128
#define PD 256
#define BN_EPS 1e-5f
#define NB1 157
#define TILE 64
#define NTILES 2510
#define PERM_SZ (NTILES * TILE)
#define ZP 64

// ---------------- device scratch (self-cleaning across replays) ----------------
__device__ int   g_deg[N_NODES];     // zeroed by k_scan3 after its last read
__device__ int   g_off[N_NODES + 1];
__device__ int   g_cur[N_NODES];
__device__ int   g_csr[N_EDGES];
__device__ int   g_didx[N_NODES];
__device__ int   g_aux[NB1];
__device__ int   g_bcnt[MAXD];       // zeroed by k_scan2 after its read
__device__ int   g_bfill[MAXD];      // fully rewritten by k_scan2 each replay
__device__ int   g_perm[PERM_SZ];    // -1-filled by k_count; valid slots rewritten by k_scan3
__device__ __align__(16) float g_zA[(size_t)N_NODES * ZP];
__device__ __align__(16) float g_zB[(size_t)N_NODES * ZP];
__device__ __align__(16) float g_sg[(size_t)N_GRAPHS * 2 * PH];
__device__ __align__(16) float g_sumL[3][64];   // per-layer BN sum accumulators
__device__ __align__(16) float g_sqL[3][64];    // per-layer BN sum-of-squares

// ---------------- packed f32x2 helpers ----------------------------------------
typedef unsigned long long u64;
__device__ __forceinline__ u64 fma2(u64 a, u64 b, u64 c) {
    u64 d; asm("fma.rn.f32x2 %0, %1, %2, %3;" : "=l"(d) : "l"(a), "l"(b), "l"(c)); return d;
}
__device__ __forceinline__ u64 add2(u64 a, u64 b) {
    u64 d; asm("add.rn.f32x2 %0, %1, %2;" : "=l"(d) : "l"(a), "l"(b)); return d;
}
__device__ __forceinline__ u64 pack2(float lo, float hi) {
    u64 d; asm("mov.b64 %0, {%1, %2};" : "=l"(d) : "f"(lo), "f"(hi)); return d;
}
__device__ __forceinline__ void unpack2(u64 v, float& lo, float& hi) {
    asm("mov.b64 {%0, %1}, %2;" : "=f"(lo), "=f"(hi) : "l"(v));
}

// ---------------- degree count + perm -1 fill (replaces k_init) --------------------
__global__ void k_count(const int* __restrict__ dst) {
    int i = blockIdx.x * blockDim.x + threadIdx.x;   // 625*256 = 160000 = N_EDGES/4
    g_perm[i] = -1;
    if (i < PERM_SZ - N_NODES) g_perm[N_NODES + i] = -1;   // tail 640 slots
    int4 d4 = ((const int4*)dst)[i];
    atomicAdd(&g_deg[d4.x], 1);
    atomicAdd(&g_deg[d4.y], 1);
    atomicAdd(&g_deg[d4.z], 1);
    atomicAdd(&g_deg[d4.w], 1);
}

// ---------------- scan1 + bucket counting --------------------------------------------
__global__ void k_scan1() {
    __shared__ int s[256];
    __shared__ int c[MAXD];
    int t = threadIdx.x;
    if (t < MAXD) c[t] = 0;
    int base = blockIdx.x * 1024;
    int v[4]; int mysum = 0;
#pragma unroll
    for (int k = 0; k < 4; k++) {
        int idx = base + t * 4 + k;
        v[k] = (idx < N_NODES) ? g_deg[idx] : 0;
        mysum += v[k];
    }
    s[t] = mysum;
    __syncthreads();
    for (int off = 1; off < 256; off <<= 1) {
        int x = (t >= off) ? s[t - off] : 0;
        __syncthreads();
        s[t] += x;
        __syncthreads();
    }
    int run = s[t] - mysum;
#pragma unroll
    for (int k = 0; k < 4; k++) {
        int idx = base + t * 4 + k;
        if (idx < N_NODES) {
            g_off[idx] = run;
            int d = v[k];
            d = (d < 1) ? 1 : (d > MAXD ? MAXD : d);
            atomicAdd(&c[d - 1], 1);
        }
        run += v[k];
    }
    if (t == 255) g_aux[blockIdx.x] = s[255];
    __syncthreads();
    if (t < MAXD && c[t] > 0) atomicAdd(&g_bcnt[t], c[t]);
}

// ---------------- scan2 + bucket offsets + zero BN accumulators + bcnt cleanup --------
__global__ void k_scan2() {
    __shared__ int s[256];
    int t = threadIdx.x;
    int v = (t < NB1) ? g_aux[t] : 0;
    s[t] = v;
    __syncthreads();
    for (int off = 1; off < 256; off <<= 1) {
        int x = (t >= off) ? s[t - off] : 0;
        __syncthreads();
        s[t] += x;
        __syncthreads();
    }
    if (t < NB1) g_aux[t] = s[t] - v;
    if (t < 64) {
#pragma unroll
        for (int l = 0; l < 3; l++) { g_sumL[l][t] = 0.f; g_sqL[l][t] = 0.f; }
    }
    if (t == 255) {
        int acc = 0;
        for (int dd = 0; dd < MAXD; dd++) {
            g_bfill[dd] = acc;
            acc += (g_bcnt[dd] + TILE - 1) / TILE * TILE;
        }
    }
    __syncthreads();                      // t==255 done reading g_bcnt
    if (t < MAXD) g_bcnt[t] = 0;          // self-clean for next replay
}

// ---------------- scan3 + didx + perm fill + deg cleanup -------------------------------
__global__ void k_scan3() {
    __shared__ int c[MAXD], base[MAXD];
    int t = threadIdx.x;
    if (t < MAXD) c[t] = 0;
    __syncthreads();
    int i = blockIdx.x * blockDim.x + t;
    int d = 0, r = 0;
    bool valid = (i < N_NODES);
    if (valid) {
        int o = g_off[i] + g_aux[i >> 10];
        g_off[i] = o;
        g_cur[i] = o;
        int dg = g_deg[i];
        g_deg[i] = 0;                     // self-clean for next replay
        dg = (dg < 1) ? 1 : (dg > MAXD ? MAXD : dg);
        d = dg - 1;
        g_didx[i] = d;
        r = atomicAdd(&c[d], 1);
    }
    if (i == 0) g_off[N_NODES] = N_EDGES;
    __syncthreads();
    if (t < MAXD && c[t] > 0) base[t] = atomicAdd(&g_bfill[t], c[t]);
    __syncthreads();
    if (valid) g_perm[base[d] + r] = i;
}

// ---------------- CSR scatter: 4 edges/thread -----------------------------------------
__global__ void k_scatter(const int* __restrict__ src, const int* __restrict__ dst) {
    int i = blockIdx.x * blockDim.x + threadIdx.x;   // 625*256 = N_EDGES/4
    int4 d4 = ((const int4*)dst)[i];
    int4 s4 = ((const int4*)src)[i];
    int p0 = atomicAdd(&g_cur[d4.x], 1);
    int p1 = atomicAdd(&g_cur[d4.y], 1);
    int p2 = atomicAdd(&g_cur[d4.z], 1);
    int p3 = atomicAdd(&g_cur[d4.w], 1);
    g_csr[p0] = s4.x;
    g_csr[p1] = s4.y;
    g_csr[p2] = s4.z;
    g_csr[p3] = s4.w;
}

// ---------------- fused NF layer (inline BN affine from prev-layer stats) -------------
// MODE 0: feats (pitch 74, no affine) -> g_zB, stats -> g_sumL[0]
// MODE 1: g_zB (affine from L0 stats) -> g_zA, stats -> g_sumL[1]
// MODE 2: g_zA (affine from L1 stats) -> g_zB, stats -> g_sumL[2]
template <int FIN, int MODE>
__global__ void __launch_bounds__(256)
k_layer(const float* __restrict__ ext_in, const float* __restrict__ W,
        const float* __restrict__ b, const float* __restrict__ gamma,
        const float* __restrict__ beta) {
    const float* in   = (MODE == 0) ? ext_in : (MODE == 1 ? g_zB : g_zA);
    float*       zout = (MODE == 1) ? g_zA : g_zB;

    constexpr int SP = 66;          // sT pitch over the 64 node slots (feature-major)
    __shared__ float sW[FIN * 64];  // [feat i][out o]
    __shared__ float sT[FIN * SP];  // [feat i][slot]
    __shared__ float sb[64];
    __shared__ float ssum[H], ssq[H];
    __shared__ __align__(16) float sScale[64], sShift[64];

    int t = threadIdx.x, w = t >> 5, lane = t & 31;
    int tbase = blockIdx.x * TILE;
    int n0 = g_perm[tbase];
    if (n0 < 0) return;
    int d = g_didx[n0];

    if (t < H) { ssum[t] = 0.f; ssq[t] = 0.f; sb[t] = b[d * H + t]; }
    if (t == 255) sb[63] = 0.f;
    if (t < FIN) sW[t * 64 + 63] = 0.f;

    // inline BN affine from previous layer's accumulated stats
    if (MODE != 0) {
        if (t < H) {
            float su = g_sumL[MODE - 1][t];
            float sq = g_sqL[MODE - 1][t];
            float mu  = su * (1.f / N_NODES);
            float var = sq * (1.f / N_NODES) - mu * mu;
            float sc  = gamma[t] * rsqrtf(var + BN_EPS);
            sScale[t] = sc;
            sShift[t] = beta[t] - mu * sc;
        } else if (t == 63) {
            sScale[63] = 0.f;
            sShift[63] = 0.f;
        }
    }

    const float* Wd = W + d * FIN * H;
    for (int idx = t; idx < FIN * H; idx += 256) {
        int i = idx / H, o = idx - i * H;
        sW[i * 64 + o] = Wd[idx];
    }
    __syncthreads();   // ONLY block-wide barrier before epilogue: protects sW/sb/sScale

    // ---- gather (warp-private sT columns; no block sync needed) ----
    if (MODE == 0) {
        const u64* in64 = (const u64*)in;
        for (int r = 0; r < 8; r++) {
            int slot = w * 8 + r;
            int n = g_perm[tbase + slot];
            if (n >= 0) {
                int s0 = g_off[n], s1 = g_off[n + 1];
                size_t rbs = (size_t)n * 37;
                u64 a0 = in64[rbs + lane];
                u64 a1 = (lane < 5) ? in64[rbs + 32 + lane] : 0ULL;
                int j = s0;
                for (; j + 4 <= s1; j += 4) {
                    int c0 = g_csr[j], c1 = g_csr[j + 1], c2 = g_csr[j + 2], c3 = g_csr[j + 3];
                    size_t r0 = (size_t)c0 * 37, r1 = (size_t)c1 * 37,
                           r2 = (size_t)c2 * 37, r3 = (size_t)c3 * 37;
                    u64 v0 = in64[r0 + lane], v1 = in64[r1 + lane],
                        v2 = in64[r2 + lane], v3 = in64[r3 + lane];
                    a0 = add2(a0, add2(add2(v0, v1), add2(v2, v3)));
                    if (lane < 5) {
                        u64 w0 = in64[r0 + 32 + lane], w1 = in64[r1 + 32 + lane],
                            w2 = in64[r2 + 32 + lane], w3 = in64[r3 + 32 + lane];
                        a1 = add2(a1, add2(add2(w0, w1), add2(w2, w3)));
                    }
                }
                for (; j < s1; j++) {
                    size_t rb = (size_t)g_csr[j] * 37;
                    a0 = add2(a0, in64[rb + lane]);
                    if (lane < 5) a1 = add2(a1, in64[rb + 32 + lane]);
                }
                float x, y;
                unpack2(a0, x, y);
                sT[(2 * lane) * SP + slot] = x;
                sT[(2 * lane + 1) * SP + slot] = y;
                if (lane < 5) {
                    unpack2(a1, x, y);
                    sT[(64 + 2 * lane) * SP + slot] = x;
                    sT[(65 + 2 * lane) * SP + slot] = y;
                }
            } else {
#pragma unroll
                for (int k = 0; k < 3; k++) {
                    int f = lane + 32 * k;
                    if (f < FIN) sT[f * SP + slot] = 0.f;
                }
            }
        }
    } else {
        // dual-row float4 gather: half-warp grp 0 = even neighbors (+self), grp 1 = odd
        const float4* in4 = (const float4*)in;
        int chunk = lane & 15, grp = lane >> 4;
        for (int r = 0; r < 8; r++) {
            int slot = w * 8 + r;
            int n = g_perm[tbase + slot];
            if (n >= 0) {
                int s0 = g_off[n], s1 = g_off[n + 1];
                float4 a;
                if (grp == 0) a = in4[(size_t)n * 16 + chunk];
                else          a = make_float4(0.f, 0.f, 0.f, 0.f);
                int j = s0 + grp;
                for (; j + 2 < s1; j += 4) {
                    int cA = g_csr[j], cB = g_csr[j + 2];
                    float4 vA = in4[(size_t)cA * 16 + chunk];
                    float4 vB = in4[(size_t)cB * 16 + chunk];
                    a.x += vA.x + vB.x;
                    a.y += vA.y + vB.y;
                    a.z += vA.z + vB.z;
                    a.w += vA.w + vB.w;
                }
                if (j < s1) {
                    float4 v = in4[(size_t)g_csr[j] * 16 + chunk];
                    a.x += v.x; a.y += v.y; a.z += v.z; a.w += v.w;
                }
                a.x += __shfl_xor_sync(0xffffffffu, a.x, 16);
                a.y += __shfl_xor_sync(0xffffffffu, a.y, 16);
                a.z += __shfl_xor_sync(0xffffffffu, a.z, 16);
                a.w += __shfl_xor_sync(0xffffffffu, a.w, 16);
                if (grp == 0) {
                    float cnt = (float)(1 + s1 - s0);
                    float4 sc = ((const float4*)sScale)[chunk];
                    float4 sh = ((const float4*)sShift)[chunk];
                    a.x = fmaf(a.x, sc.x, cnt * sh.x);
                    a.y = fmaf(a.y, sc.y, cnt * sh.y);
                    a.z = fmaf(a.z, sc.z, cnt * sh.z);
                    a.w = fmaf(a.w, sc.w, cnt * sh.w);
                    int f = 4 * chunk;
                    sT[(f + 0) * SP + slot] = a.x;
                    sT[(f + 1) * SP + slot] = a.y;
                    sT[(f + 2) * SP + slot] = a.z;
                    sT[(f + 3) * SP + slot] = a.w;
                }
            } else if (grp == 0) {
                int f = 4 * chunk;
                sT[(f + 0) * SP + slot] = 0.f;
                sT[(f + 1) * SP + slot] = 0.f;
                sT[(f + 2) * SP + slot] = 0.f;
                sT[(f + 3) * SP + slot] = 0.f;
            }
        }
    }
    __syncwarp();   // warp-private sT ready

    // ---- GEMM: warp = its own 8 nodes (4 pairs) x 63 outputs via FFMA2 ----
    u64 z0[4], z1[4];
    float bb0 = sb[lane];
    float bb1 = (lane < H - 32) ? sb[32 + lane] : 0.f;
    u64 b0d = pack2(bb0, bb0), b1d = pack2(bb1, bb1);
#pragma unroll
    for (int p = 0; p < 4; p++) { z0[p] = b0d; z1[p] = b1d; }

    int slotbase = w * 8;
    int loop_fin = (MODE == 0) ? FIN : H;
    for (int i = 0; i < loop_fin; i++) {
        float w0 = sW[i * 64 + lane];
        float w1 = sW[i * 64 + 32 + lane];
        u64 w0d = pack2(w0, w0), w1d = pack2(w1, w1);
        const u64* tp = (const u64*)&sT[i * SP + slotbase];
#pragma unroll
        for (int p = 0; p < 4; p++) {
            u64 tv = tp[p];
            z0[p] = fma2(tv, w0d, z0[p]);
            z1[p] = fma2(tv, w1d, z1[p]);
        }
    }

    // ---- epilogue: relu + store + BN stats (smem aggregation) ----
    float rs0 = 0.f, rq0 = 0.f, rs1 = 0.f, rq1 = 0.f;
#pragma unroll
    for (int p = 0; p < 4; p++) {
        float a, bv, c2, dv;
        unpack2(z0[p], a, bv);
        unpack2(z1[p], c2, dv);
        int sA = tbase + slotbase + 2 * p;
        int nA = g_perm[sA];
        int nB = g_perm[sA + 1];
        if (nA >= 0) {
            a = fmaxf(a, 0.f); c2 = fmaxf(c2, 0.f);
            zout[(size_t)nA * ZP + lane] = a; rs0 += a; rq0 += a * a;
            if (lane < H - 32) { zout[(size_t)nA * ZP + 32 + lane] = c2; rs1 += c2; rq1 += c2 * c2; }
        }
        if (nB >= 0) {
            bv = fmaxf(bv, 0.f); dv = fmaxf(dv, 0.f);
            zout[(size_t)nB * ZP + lane] = bv; rs0 += bv; rq0 += bv * bv;
            if (lane < H - 32) { zout[(size_t)nB * ZP + 32 + lane] = dv; rs1 += dv; rq1 += dv * dv; }
        }
    }
    atomicAdd(&ssum[lane], rs0);
    atomicAdd(&ssq[lane], rq0);
    if (lane < H - 32) {
        atomicAdd(&ssum[32 + lane], rs1);
        atomicAdd(&ssq[32 + lane], rq1);
    }
    __syncthreads();
    if (t < H) {
        atomicAdd(&g_sumL[MODE][t], ssum[t]);
        atomicAdd(&g_sqL[MODE][t], ssq[t]);
    }
}

// ---------------- fused node->graph GEMM + readout (inline L2-BN fold of W_ng) --------
#define NGF_G 8
__global__ void __launch_bounds__(256)
k_ngf(const float* __restrict__ Wng, const float* __restrict__ bng,
      const float* __restrict__ gamma, const float* __restrict__ beta) {
    extern __shared__ float sm[];
    float* sW = sm;                       // 63*128
    float* sT = sm + H * PH;              // 63*160
    float* sStage = sT + H * 160;         // 32*65

    __shared__ float sS[64], sHH[64];
    __shared__ float sbp[PH];

    int t = threadIdx.x, w = t >> 5, lane = t & 31;
    int nb = blockIdx.x * (NGF_G * NPG);

    // per-block BN affine for layer 2 (replaces k_fold launch)
    if (t < H) {
        float su = g_sumL[2][t];
        float sq = g_sqL[2][t];
        float mu  = su * (1.f / N_NODES);
        float var = sq * (1.f / N_NODES) - mu * mu;
        float sc  = gamma[t] * rsqrtf(var + BN_EPS);
        sS[t] = sc;
        sHH[t] = beta[t] - mu * sc;
    }
    __syncthreads();

    // fold affine into W_ng while loading to smem; fold shift into bias.
    // threads 0..127 each own output column t.
    if (t < PH) {
        float acc = bng[t];
        for (int i = 0; i < H; i++) {
            float wv = Wng[i * PH + t];
            sW[i * PH + t] = sS[i] * wv;
            acc = fmaf(sHH[i], wv, acc);
        }
        sbp[t] = acc;
    }

    const u64* z64 = (const u64*)g_zB;
    for (int wv = 0; wv < 5; wv++) {
#pragma unroll
        for (int r = 0; r < 4; r++) {
            int idx = t + 256 * r;
            int fp = idx & 31, nl = idx >> 5;
            u64 v = z64[(size_t)(nb + wv * 32 + nl) * 32 + fp];
            float x, y;
            unpack2(v, x, y);
            sStage[nl * 65 + 2 * fp] = x;
            sStage[nl * 65 + 2 * fp + 1] = y;
        }
        __syncthreads();
        for (int k = t; k < 32 * H; k += 256) {
            int nl = k & 31, f = k >> 5;
            sT[f * 160 + wv * 32 + nl] = sStage[nl * 65 + f];
        }
        __syncthreads();
    }

    float s[4], m[4];
#pragma unroll
    for (int j = 0; j < 4; j++) { s[j] = 0.f; m[j] = -3.402823466e38f; }

#pragma unroll
    for (int op2 = 0; op2 < 2; op2++) {
#pragma unroll
        for (int c = 0; c < 2; c++) {
            u64 z[5][2];
#pragma unroll
            for (int p = 0; p < 5; p++) { z[p][0] = 0ULL; z[p][1] = 0ULL; }
            for (int i = 0; i < H; i++) {
                const u64* tp = (const u64*)&sT[i * 160 + w * NPG + c * 10];
                float w0 = sW[i * PH + lane + 64 * op2];
                float w1 = sW[i * PH + lane + 32 + 64 * op2];
                u64 w0d = pack2(w0, w0), w1d = pack2(w1, w1);
#pragma unroll
                for (int p = 0; p < 5; p++) {
                    u64 tv = tp[p];
                    z[p][0] = fma2(tv, w0d, z[p][0]);
                    z[p][1] = fma2(tv, w1d, z[p][1]);
                }
            }
#pragma unroll
            for (int p = 0; p < 5; p++) {
#pragma unroll
                for (int q = 0; q < 2; q++) {
                    float a, bv;
                    unpack2(z[p][q], a, bv);
                    int j = op2 * 2 + q;
                    s[j] += a + bv;
                    m[j] = fmaxf(m[j], fmaxf(a, bv));
                }
            }
        }
    }

    int graph = blockIdx.x * NGF_G + w;
#pragma unroll
    for (int j = 0; j < 4; j++) {
        int o = lane + 32 * (j & 1) + 64 * (j >> 1);
        float bo = sbp[o];
        g_sg[(size_t)graph * 2 * PH + o]      = tanhf(s[j] + (float)NPG * bo);
        g_sg[(size_t)graph * 2 * PH + PH + o] = tanhf(m[j] + bo);
    }
}
#define NGF_SMEM ((H * PH + H * 160 + 32 * 65) * 4)

// ---------------- final GEMM: out = sg @ W_tr + b_tr ---------------------------------
#define GPB 32
__global__ void __launch_bounds__(256)
k_out(const float* __restrict__ Wtr, const float* __restrict__ btr,
      float* __restrict__ out) {
    __shared__ float sgT[2 * PH * 34];   // [feat][graph], pitch 34
    int t = threadIdx.x;
    int g0 = blockIdx.x * GPB;

    for (int k = t; k < GPB * 2 * PH; k += 256) {
        int f = k & 255, gl = k >> 8;
        sgT[f * 34 + gl] = g_sg[(size_t)(g0 + gl) * 2 * PH + f];
    }
    __syncthreads();

    float bb = btr[t];
    u64 z[GPB / 2];
    u64 bbd = pack2(bb, bb);
#pragma unroll
    for (int p = 0; p < GPB / 2; p++) z[p] = bbd;

    for (int i = 0; i < 2 * PH; i++) {
        float wv = Wtr[i * PD + t];
        u64 wvd = pack2(wv, wv);
        const u64* tp = (const u64*)&sgT[i * 34];
#pragma unroll
        for (int p = 0; p < GPB / 2; p++) z[p] = fma2(tp[p], wvd, z[p]);
    }
#pragma unroll
    for (int p = 0; p < GPB / 2; p++) {
        float a, b2;
        unpack2(z[p], a, b2);
        out[(size_t)(g0 + 2 * p) * PD + t] = a;
        out[(size_t)(g0 + 2 * p + 1) * PD + t] = b2;
    }
}

// ---------------- launch ---------------------------------------------------------------
extern "C" void kernel_launch(void* const* d_in, const int* in_sizes, int n_in,
                              void* d_out, int out_size) {
    const float* feats = (const float*)d_in[0];
    const int*   src   = (const int*)d_in[1];
    const int*   dst   = (const int*)d_in[2];
    const float* W0  = (const float*)d_in[4];
    const float* b0  = (const float*)d_in[5];
    const float* g0  = (const float*)d_in[6];
    const float* be0 = (const float*)d_in[7];
    const float* W1  = (const float*)d_in[8];
    const float* b1  = (const float*)d_in[9];
    const float* g1  = (const float*)d_in[10];
    const float* be1 = (const float*)d_in[11];
    const float* W2  = (const float*)d_in[12];
    const float* b2  = (const float*)d_in[13];
    const float* g2  = (const float*)d_in[14];
    const float* be2 = (const float*)d_in[15];
    const float* Wng = (const float*)d_in[16];
    const float* bng = (const float*)d_in[17];
    const float* Wtr = (const float*)d_in[18];
    const float* btr = (const float*)d_in[19];
    float* out = (float*)d_out;

    static bool attr_done = false;
    if (!attr_done) {
        cudaFuncSetAttribute(k_ngf, cudaFuncAttributeMaxDynamicSharedMemorySize, NGF_SMEM);
        attr_done = true;
    }

    // graph build + degree-bucket sort (self-cleaning; no k_init)
    k_count<<<N_EDGES / 4 / 256, 256>>>(dst);
    k_scan1<<<NB1, 256>>>();
    k_scan2<<<1, 256>>>();
    k_scan3<<<(N_NODES + 255) / 256, 256>>>();
    k_scatter<<<N_EDGES / 4 / 256, 256>>>(src, dst);

    // 3 NF layers — BN affine computed inline per block from prev layer's stats
    k_layer<F0, 0><<<NTILES, 256>>>(feats, W0, b0, nullptr, nullptr);
    k_layer<H, 1><<<NTILES, 256>>>(nullptr, W1, b1, g0, be0);
    k_layer<H, 2><<<NTILES, 256>>>(nullptr, W2, b2, g1, be1);

    // fused node->graph GEMM + readout (inline L2-BN fold), final GEMM
    k_ngf<<<N_GRAPHS / NGF_G, 256, NGF_SMEM>>>(Wng, bng, g2, be2);
    k_out<<<N_GRAPHS / GPB, 256>>>(Wtr, btr, out);
}

// round 17
// speedup vs baseline: 1.0096x; 1.0096x over previous
#include <cuda_runtime.h>
#include <math.h>
#include <stdint.h>

#define N_NODES 160000
#define N_EDGES 640000
#define N_GRAPHS 8000
#define NPG 20
#define F0 74
#define H 63
#define MAXD 10
#define PH 128
#define PD 256
#define BN_EPS 1e-5f
#define NB1 157
#define TILE 64
#define NTILES 2510
#define PERM_SZ (NTILES * TILE)
#define ZP 64

// ---------------- device scratch (self-cleaning across replays) ----------------
__device__ int   g_deg[N_NODES];     // zeroed by k_scan3 after its last read
__device__ int   g_off[N_NODES + 1];
__device__ int   g_cur[N_NODES];
__device__ int   g_csr[N_EDGES];
__device__ int   g_didx[N_NODES];
__device__ int   g_aux[NB1];
__device__ int   g_bcnt[MAXD];       // zeroed by k_scan2 after its read
__device__ int   g_bfill[MAXD];      // fully rewritten by k_scan2 each replay
__device__ int   g_perm[PERM_SZ];    // -1-filled by k_count; valid slots rewritten by k_scan3
__device__ __align__(16) float g_zA[(size_t)N_NODES * ZP];
__device__ __align__(16) float g_zB[(size_t)N_NODES * ZP];
__device__ __align__(16) float g_sg[(size_t)N_GRAPHS * 2 * PH];
__device__ __align__(16) float g_sumL[3][64];   // per-layer BN sum accumulators
__device__ __align__(16) float g_sqL[3][64];    // per-layer BN sum-of-squares
__device__ __align__(16) float g_Wp[H * PH];
__device__ __align__(16) float g_bp[PH];

// ---------------- packed f32x2 helpers ----------------------------------------
typedef unsigned long long u64;
__device__ __forceinline__ u64 fma2(u64 a, u64 b, u64 c) {
    u64 d; asm("fma.rn.f32x2 %0, %1, %2, %3;" : "=l"(d) : "l"(a), "l"(b), "l"(c)); return d;
}
__device__ __forceinline__ u64 add2(u64 a, u64 b) {
    u64 d; asm("add.rn.f32x2 %0, %1, %2;" : "=l"(d) : "l"(a), "l"(b)); return d;
}
__device__ __forceinline__ u64 pack2(float lo, float hi) {
    u64 d; asm("mov.b64 %0, {%1, %2};" : "=l"(d) : "f"(lo), "f"(hi)); return d;
}
__device__ __forceinline__ void unpack2(u64 v, float& lo, float& hi) {
    asm("mov.b64 {%0, %1}, %2;" : "=f"(lo), "=f"(hi) : "l"(v));
}

// ---------------- degree count + perm -1 fill (replaces k_init) --------------------
__global__ void k_count(const int* __restrict__ dst) {
    int i = blockIdx.x * blockDim.x + threadIdx.x;   // 625*256 = 160000 = N_EDGES/4
    g_perm[i] = -1;
    if (i < PERM_SZ - N_NODES) g_perm[N_NODES + i] = -1;   // tail 640 slots
    int4 d4 = ((const int4*)dst)[i];
    atomicAdd(&g_deg[d4.x], 1);
    atomicAdd(&g_deg[d4.y], 1);
    atomicAdd(&g_deg[d4.z], 1);
    atomicAdd(&g_deg[d4.w], 1);
}

// ---------------- scan1 + bucket counting --------------------------------------------
__global__ void k_scan1() {
    __shared__ int s[256];
    __shared__ int c[MAXD];
    int t = threadIdx.x;
    if (t < MAXD) c[t] = 0;
    int base = blockIdx.x * 1024;
    int v[4]; int mysum = 0;
#pragma unroll
    for (int k = 0; k < 4; k++) {
        int idx = base + t * 4 + k;
        v[k] = (idx < N_NODES) ? g_deg[idx] : 0;
        mysum += v[k];
    }
    s[t] = mysum;
    __syncthreads();
    for (int off = 1; off < 256; off <<= 1) {
        int x = (t >= off) ? s[t - off] : 0;
        __syncthreads();
        s[t] += x;
        __syncthreads();
    }
    int run = s[t] - mysum;
#pragma unroll
    for (int k = 0; k < 4; k++) {
        int idx = base + t * 4 + k;
        if (idx < N_NODES) {
            g_off[idx] = run;
            int d = v[k];
            d = (d < 1) ? 1 : (d > MAXD ? MAXD : d);
            atomicAdd(&c[d - 1], 1);
        }
        run += v[k];
    }
    if (t == 255) g_aux[blockIdx.x] = s[255];
    __syncthreads();
    if (t < MAXD && c[t] > 0) atomicAdd(&g_bcnt[t], c[t]);
}

// ---------------- scan2 + bucket offsets + zero BN accumulators + bcnt cleanup --------
__global__ void k_scan2() {
    __shared__ int s[256];
    int t = threadIdx.x;
    int v = (t < NB1) ? g_aux[t] : 0;
    s[t] = v;
    __syncthreads();
    for (int off = 1; off < 256; off <<= 1) {
        int x = (t >= off) ? s[t - off] : 0;
        __syncthreads();
        s[t] += x;
        __syncthreads();
    }
    if (t < NB1) g_aux[t] = s[t] - v;
    if (t < 64) {
#pragma unroll
        for (int l = 0; l < 3; l++) { g_sumL[l][t] = 0.f; g_sqL[l][t] = 0.f; }
    }
    if (t == 255) {
        int acc = 0;
        for (int dd = 0; dd < MAXD; dd++) {
            g_bfill[dd] = acc;
            acc += (g_bcnt[dd] + TILE - 1) / TILE * TILE;
        }
    }
    __syncthreads();                      // t==255 done reading g_bcnt
    if (t < MAXD) g_bcnt[t] = 0;          // self-clean for next replay
}

// ---------------- scan3 + didx + perm fill + deg cleanup -------------------------------
__global__ void k_scan3() {
    __shared__ int c[MAXD], base[MAXD];
    int t = threadIdx.x;
    if (t < MAXD) c[t] = 0;
    __syncthreads();
    int i = blockIdx.x * blockDim.x + t;
    int d = 0, r = 0;
    bool valid = (i < N_NODES);
    if (valid) {
        int o = g_off[i] + g_aux[i >> 10];
        g_off[i] = o;
        g_cur[i] = o;
        int dg = g_deg[i];
        g_deg[i] = 0;                     // self-clean for next replay
        dg = (dg < 1) ? 1 : (dg > MAXD ? MAXD : dg);
        d = dg - 1;
        g_didx[i] = d;
        r = atomicAdd(&c[d], 1);
    }
    if (i == 0) g_off[N_NODES] = N_EDGES;
    __syncthreads();
    if (t < MAXD && c[t] > 0) base[t] = atomicAdd(&g_bfill[t], c[t]);
    __syncthreads();
    if (valid) g_perm[base[d] + r] = i;
}

// ---------------- CSR scatter: 4 edges/thread -----------------------------------------
__global__ void k_scatter(const int* __restrict__ src, const int* __restrict__ dst) {
    int i = blockIdx.x * blockDim.x + threadIdx.x;   // 625*256 = N_EDGES/4
    int4 d4 = ((const int4*)dst)[i];
    int4 s4 = ((const int4*)src)[i];
    int p0 = atomicAdd(&g_cur[d4.x], 1);
    int p1 = atomicAdd(&g_cur[d4.y], 1);
    int p2 = atomicAdd(&g_cur[d4.z], 1);
    int p3 = atomicAdd(&g_cur[d4.w], 1);
    g_csr[p0] = s4.x;
    g_csr[p1] = s4.y;
    g_csr[p2] = s4.z;
    g_csr[p3] = s4.w;
}

// ---------------- fused NF layer (inline BN affine from prev-layer stats) -------------
// MODE 0: feats (pitch 74, no affine) -> g_zB, stats -> g_sumL[0]
// MODE 1: g_zB (affine from L0 stats) -> g_zA, stats -> g_sumL[1]
// MODE 2: g_zA (affine from L1 stats) -> g_zB, stats -> g_sumL[2]
template <int FIN, int MODE>
__global__ void __launch_bounds__(256)
k_layer(const float* __restrict__ ext_in, const float* __restrict__ W,
        const float* __restrict__ b, const float* __restrict__ gamma,
        const float* __restrict__ beta) {
    const float* in   = (MODE == 0) ? ext_in : (MODE == 1 ? g_zB : g_zA);
    float*       zout = (MODE == 1) ? g_zA : g_zB;

    constexpr int SP = 66;          // sT pitch over the 64 node slots (feature-major)
    __shared__ float sW[FIN * 64];  // [feat i][out o]
    __shared__ float sT[FIN * SP];  // [feat i][slot]
    __shared__ float sb[64];
    __shared__ float ssum[H], ssq[H];
    __shared__ __align__(16) float sScale[64], sShift[64];

    int t = threadIdx.x, w = t >> 5, lane = t & 31;
    int tbase = blockIdx.x * TILE;
    int n0 = g_perm[tbase];
    if (n0 < 0) return;
    int d = g_didx[n0];

    if (t < H) { ssum[t] = 0.f; ssq[t] = 0.f; sb[t] = b[d * H + t]; }
    if (t == 255) sb[63] = 0.f;
    if (t < FIN) sW[t * 64 + 63] = 0.f;

    // inline BN affine from previous layer's accumulated stats
    if (MODE != 0) {
        if (t < H) {
            float su = g_sumL[MODE - 1][t];
            float sq = g_sqL[MODE - 1][t];
            float mu  = su * (1.f / N_NODES);
            float var = sq * (1.f / N_NODES) - mu * mu;
            float sc  = gamma[t] * rsqrtf(var + BN_EPS);
            sScale[t] = sc;
            sShift[t] = beta[t] - mu * sc;
        } else if (t == 63) {
            sScale[63] = 0.f;
            sShift[63] = 0.f;
        }
    }

    const float* Wd = W + d * FIN * H;
    for (int idx = t; idx < FIN * H; idx += 256) {
        int i = idx / H, o = idx - i * H;
        sW[i * 64 + o] = Wd[idx];
    }
    __syncthreads();   // ONLY block-wide barrier before epilogue: protects sW/sb/sScale

    // ---- gather (warp-private sT columns; no block sync needed) ----
    if (MODE == 0) {
        const u64* in64 = (const u64*)in;
        for (int r = 0; r < 8; r++) {
            int slot = w * 8 + r;
            int n = g_perm[tbase + slot];
            if (n >= 0) {
                int s0 = g_off[n], s1 = g_off[n + 1];
                size_t rbs = (size_t)n * 37;
                u64 a0 = in64[rbs + lane];
                u64 a1 = (lane < 5) ? in64[rbs + 32 + lane] : 0ULL;
                int j = s0;
                for (; j + 4 <= s1; j += 4) {
                    int c0 = g_csr[j], c1 = g_csr[j + 1], c2 = g_csr[j + 2], c3 = g_csr[j + 3];
                    size_t r0 = (size_t)c0 * 37, r1 = (size_t)c1 * 37,
                           r2 = (size_t)c2 * 37, r3 = (size_t)c3 * 37;
                    u64 v0 = in64[r0 + lane], v1 = in64[r1 + lane],
                        v2 = in64[r2 + lane], v3 = in64[r3 + lane];
                    a0 = add2(a0, add2(add2(v0, v1), add2(v2, v3)));
                    if (lane < 5) {
                        u64 w0 = in64[r0 + 32 + lane], w1 = in64[r1 + 32 + lane],
                            w2 = in64[r2 + 32 + lane], w3 = in64[r3 + 32 + lane];
                        a1 = add2(a1, add2(add2(w0, w1), add2(w2, w3)));
                    }
                }
                for (; j < s1; j++) {
                    size_t rb = (size_t)g_csr[j] * 37;
                    a0 = add2(a0, in64[rb + lane]);
                    if (lane < 5) a1 = add2(a1, in64[rb + 32 + lane]);
                }
                float x, y;
                unpack2(a0, x, y);
                sT[(2 * lane) * SP + slot] = x;
                sT[(2 * lane + 1) * SP + slot] = y;
                if (lane < 5) {
                    unpack2(a1, x, y);
                    sT[(64 + 2 * lane) * SP + slot] = x;
                    sT[(65 + 2 * lane) * SP + slot] = y;
                }
            } else {
#pragma unroll
                for (int k = 0; k < 3; k++) {
                    int f = lane + 32 * k;
                    if (f < FIN) sT[f * SP + slot] = 0.f;
                }
            }
        }
    } else {
        // dual-row float4 gather: half-warp grp 0 = even neighbors (+self), grp 1 = odd
        const float4* in4 = (const float4*)in;
        int chunk = lane & 15, grp = lane >> 4;
        for (int r = 0; r < 8; r++) {
            int slot = w * 8 + r;
            int n = g_perm[tbase + slot];
            if (n >= 0) {
                int s0 = g_off[n], s1 = g_off[n + 1];
                float4 a;
                if (grp == 0) a = in4[(size_t)n * 16 + chunk];
                else          a = make_float4(0.f, 0.f, 0.f, 0.f);
                int j = s0 + grp;
                for (; j + 2 < s1; j += 4) {
                    int cA = g_csr[j], cB = g_csr[j + 2];
                    float4 vA = in4[(size_t)cA * 16 + chunk];
                    float4 vB = in4[(size_t)cB * 16 + chunk];
                    a.x += vA.x + vB.x;
                    a.y += vA.y + vB.y;
                    a.z += vA.z + vB.z;
                    a.w += vA.w + vB.w;
                }
                if (j < s1) {
                    float4 v = in4[(size_t)g_csr[j] * 16 + chunk];
                    a.x += v.x; a.y += v.y; a.z += v.z; a.w += v.w;
                }
                a.x += __shfl_xor_sync(0xffffffffu, a.x, 16);
                a.y += __shfl_xor_sync(0xffffffffu, a.y, 16);
                a.z += __shfl_xor_sync(0xffffffffu, a.z, 16);
                a.w += __shfl_xor_sync(0xffffffffu, a.w, 16);
                if (grp == 0) {
                    float cnt = (float)(1 + s1 - s0);
                    float4 sc = ((const float4*)sScale)[chunk];
                    float4 sh = ((const float4*)sShift)[chunk];
                    a.x = fmaf(a.x, sc.x, cnt * sh.x);
                    a.y = fmaf(a.y, sc.y, cnt * sh.y);
                    a.z = fmaf(a.z, sc.z, cnt * sh.z);
                    a.w = fmaf(a.w, sc.w, cnt * sh.w);
                    int f = 4 * chunk;
                    sT[(f + 0) * SP + slot] = a.x;
                    sT[(f + 1) * SP + slot] = a.y;
                    sT[(f + 2) * SP + slot] = a.z;
                    sT[(f + 3) * SP + slot] = a.w;
                }
            } else if (grp == 0) {
                int f = 4 * chunk;
                sT[(f + 0) * SP + slot] = 0.f;
                sT[(f + 1) * SP + slot] = 0.f;
                sT[(f + 2) * SP + slot] = 0.f;
                sT[(f + 3) * SP + slot] = 0.f;
            }
        }
    }
    __syncwarp();   // warp-private sT ready

    // ---- GEMM: warp = its own 8 nodes (4 pairs) x 63 outputs via FFMA2 ----
    u64 z0[4], z1[4];
    float bb0 = sb[lane];
    float bb1 = (lane < H - 32) ? sb[32 + lane] : 0.f;
    u64 b0d = pack2(bb0, bb0), b1d = pack2(bb1, bb1);
#pragma unroll
    for (int p = 0; p < 4; p++) { z0[p] = b0d; z1[p] = b1d; }

    int slotbase = w * 8;
    int loop_fin = (MODE == 0) ? FIN : H;
    for (int i = 0; i < loop_fin; i++) {
        float w0 = sW[i * 64 + lane];
        float w1 = sW[i * 64 + 32 + lane];
        u64 w0d = pack2(w0, w0), w1d = pack2(w1, w1);
        const u64* tp = (const u64*)&sT[i * SP + slotbase];
#pragma unroll
        for (int p = 0; p < 4; p++) {
            u64 tv = tp[p];
            z0[p] = fma2(tv, w0d, z0[p]);
            z1[p] = fma2(tv, w1d, z1[p]);
        }
    }

    // ---- epilogue: relu + store + BN stats (smem aggregation) ----
    float rs0 = 0.f, rq0 = 0.f, rs1 = 0.f, rq1 = 0.f;
#pragma unroll
    for (int p = 0; p < 4; p++) {
        float a, bv, c2, dv;
        unpack2(z0[p], a, bv);
        unpack2(z1[p], c2, dv);
        int sA = tbase + slotbase + 2 * p;
        int nA = g_perm[sA];
        int nB = g_perm[sA + 1];
        if (nA >= 0) {
            a = fmaxf(a, 0.f); c2 = fmaxf(c2, 0.f);
            zout[(size_t)nA * ZP + lane] = a; rs0 += a; rq0 += a * a;
            if (lane < H - 32) { zout[(size_t)nA * ZP + 32 + lane] = c2; rs1 += c2; rq1 += c2 * c2; }
        }
        if (nB >= 0) {
            bv = fmaxf(bv, 0.f); dv = fmaxf(dv, 0.f);
            zout[(size_t)nB * ZP + lane] = bv; rs0 += bv; rq0 += bv * bv;
            if (lane < H - 32) { zout[(size_t)nB * ZP + 32 + lane] = dv; rs1 += dv; rq1 += dv * dv; }
        }
    }
    atomicAdd(&ssum[lane], rs0);
    atomicAdd(&ssq[lane], rq0);
    if (lane < H - 32) {
        atomicAdd(&ssum[32 + lane], rs1);
        atomicAdd(&ssq[32 + lane], rq1);
    }
    __syncthreads();
    if (t < H) {
        atomicAdd(&g_sumL[MODE][t], ssum[t]);
        atomicAdd(&g_sqL[MODE][t], ssq[t]);
    }
}

// ---------------- fold last BN affine into W_ng/b_ng (inline stats) -------------------
__global__ void k_fold(const float* __restrict__ Wng, const float* __restrict__ bng,
                       const float* __restrict__ gamma, const float* __restrict__ beta) {
    __shared__ float sS[64], sHH[64];
    int t = threadIdx.x;  // 128
    if (t < H) {
        float su = g_sumL[2][t];
        float sq = g_sqL[2][t];
        float mu  = su * (1.f / N_NODES);
        float var = sq * (1.f / N_NODES) - mu * mu;
        float sc  = gamma[t] * rsqrtf(var + BN_EPS);
        sS[t] = sc;
        sHH[t] = beta[t] - mu * sc;
    }
    __syncthreads();
    float acc = bng[t];
    for (int i = 0; i < H; i++) {
        float w = Wng[i * PH + t];
        g_Wp[i * PH + t] = sS[i] * w;
        acc += sHH[i] * w;
    }
    g_bp[t] = acc;
}

// ---------------- fused node->graph GEMM + sum/max readout + tanh --------------------
#define NGF_G 8
__global__ void __launch_bounds__(256)
k_ngf() {
    extern __shared__ float sm[];
    float* sW = sm;                       // 63*128
    float* sT = sm + H * PH;              // 63*160
    float* sStage = sT + H * 160;         // 32*65

    int t = threadIdx.x, w = t >> 5, lane = t & 31;
    int nb = blockIdx.x * (NGF_G * NPG);

    for (int k = t; k < H * PH; k += 256) sW[k] = g_Wp[k];

    const u64* z64 = (const u64*)g_zB;
    for (int wv = 0; wv < 5; wv++) {
#pragma unroll
        for (int r = 0; r < 4; r++) {
            int idx = t + 256 * r;
            int fp = idx & 31, nl = idx >> 5;
            u64 v = z64[(size_t)(nb + wv * 32 + nl) * 32 + fp];
            float x, y;
            unpack2(v, x, y);
            sStage[nl * 65 + 2 * fp] = x;
            sStage[nl * 65 + 2 * fp + 1] = y;
        }
        __syncthreads();
        for (int k = t; k < 32 * H; k += 256) {
            int nl = k & 31, f = k >> 5;
            sT[f * 160 + wv * 32 + nl] = sStage[nl * 65 + f];
        }
        __syncthreads();
    }

    float s[4], m[4];
#pragma unroll
    for (int j = 0; j < 4; j++) { s[j] = 0.f; m[j] = -3.402823466e38f; }

#pragma unroll
    for (int op2 = 0; op2 < 2; op2++) {
#pragma unroll
        for (int c = 0; c < 2; c++) {
            u64 z[5][2];
#pragma unroll
            for (int p = 0; p < 5; p++) { z[p][0] = 0ULL; z[p][1] = 0ULL; }
            for (int i = 0; i < H; i++) {
                const u64* tp = (const u64*)&sT[i * 160 + w * NPG + c * 10];
                float w0 = sW[i * PH + lane + 64 * op2];
                float w1 = sW[i * PH + lane + 32 + 64 * op2];
                u64 w0d = pack2(w0, w0), w1d = pack2(w1, w1);
#pragma unroll
                for (int p = 0; p < 5; p++) {
                    u64 tv = tp[p];
                    z[p][0] = fma2(tv, w0d, z[p][0]);
                    z[p][1] = fma2(tv, w1d, z[p][1]);
                }
            }
#pragma unroll
            for (int p = 0; p < 5; p++) {
#pragma unroll
                for (int q = 0; q < 2; q++) {
                    float a, bv;
                    unpack2(z[p][q], a, bv);
                    int j = op2 * 2 + q;
                    s[j] += a + bv;
                    m[j] = fmaxf(m[j], fmaxf(a, bv));
                }
            }
        }
    }

    int graph = blockIdx.x * NGF_G + w;
#pragma unroll
    for (int j = 0; j < 4; j++) {
        int o = lane + 32 * (j & 1) + 64 * (j >> 1);
        float bo = g_bp[o];
        g_sg[(size_t)graph * 2 * PH + o]      = tanhf(s[j] + (float)NPG * bo);
        g_sg[(size_t)graph * 2 * PH + PH + o] = tanhf(m[j] + bo);
    }
}
#define NGF_SMEM ((H * PH + H * 160 + 32 * 65) * 4)

// ---------------- final GEMM: out = sg @ W_tr + b_tr ---------------------------------
#define GPB 32
__global__ void __launch_bounds__(256)
k_out(const float* __restrict__ Wtr, const float* __restrict__ btr,
      float* __restrict__ out) {
    __shared__ float sgT[2 * PH * 34];   // [feat][graph], pitch 34
    int t = threadIdx.x;
    int g0 = blockIdx.x * GPB;

    for (int k = t; k < GPB * 2 * PH; k += 256) {
        int f = k & 255, gl = k >> 8;
        sgT[f * 34 + gl] = g_sg[(size_t)(g0 + gl) * 2 * PH + f];
    }
    __syncthreads();

    float bb = btr[t];
    u64 z[GPB / 2];
    u64 bbd = pack2(bb, bb);
#pragma unroll
    for (int p = 0; p < GPB / 2; p++) z[p] = bbd;

    for (int i = 0; i < 2 * PH; i++) {
        float wv = Wtr[i * PD + t];
        u64 wvd = pack2(wv, wv);
        const u64* tp = (const u64*)&sgT[i * 34];
#pragma unroll
        for (int p = 0; p < GPB / 2; p++) z[p] = fma2(tp[p], wvd, z[p]);
    }
#pragma unroll
    for (int p = 0; p < GPB / 2; p++) {
        float a, b2;
        unpack2(z[p], a, b2);
        out[(size_t)(g0 + 2 * p) * PD + t] = a;
        out[(size_t)(g0 + 2 * p + 1) * PD + t] = b2;
    }
}

// ---------------- launch ---------------------------------------------------------------
extern "C" void kernel_launch(void* const* d_in, const int* in_sizes, int n_in,
                              void* d_out, int out_size) {
    const float* feats = (const float*)d_in[0];
    const int*   src   = (const int*)d_in[1];
    const int*   dst   = (const int*)d_in[2];
    const float* W0  = (const float*)d_in[4];
    const float* b0  = (const float*)d_in[5];
    const float* g0  = (const float*)d_in[6];
    const float* be0 = (const float*)d_in[7];
    const float* W1  = (const float*)d_in[8];
    const float* b1  = (const float*)d_in[9];
    const float* g1  = (const float*)d_in[10];
    const float* be1 = (const float*)d_in[11];
    const float* W2  = (const float*)d_in[12];
    const float* b2  = (const float*)d_in[13];
    const float* g2  = (const float*)d_in[14];
    const float* be2 = (const float*)d_in[15];
    const float* Wng = (const float*)d_in[16];
    const float* bng = (const float*)d_in[17];
    const float* Wtr = (const float*)d_in[18];
    const float* btr = (const float*)d_in[19];
    float* out = (float*)d_out;

    static bool attr_done = false;
    if (!attr_done) {
        cudaFuncSetAttribute(k_ngf, cudaFuncAttributeMaxDynamicSharedMemorySize, NGF_SMEM);
        attr_done = true;
    }

    // graph build + degree-bucket sort (self-cleaning; no k_init)
    k_count<<<N_EDGES / 4 / 256, 256>>>(dst);
    k_scan1<<<NB1, 256>>>();
    k_scan2<<<1, 256>>>();
    k_scan3<<<(N_NODES + 255) / 256, 256>>>();
    k_scatter<<<N_EDGES / 4 / 256, 256>>>(src, dst);

    // 3 NF layers — BN affine computed inline per block from prev layer's stats
    k_layer<F0, 0><<<NTILES, 256>>>(feats, W0, b0, nullptr, nullptr);
    k_layer<H, 1><<<NTILES, 256>>>(nullptr, W1, b1, g0, be0);
    k_layer<H, 2><<<NTILES, 256>>>(nullptr, W2, b2, g1, be1);

    // fold last BN affine + W_ng (single launch), fused readout GEMM, final GEMM
    k_fold<<<1, PH>>>(Wng, bng, g2, be2);
    k_ngf<<<N_GRAPHS / NGF_G, 256, NGF_SMEM>>>();
    k_out<<<N_GRAPHS / GPB, 256>>>(Wtr, btr, out);
}